// round 10
// baseline (speedup 1.0000x reference)
#include <cuda_runtime.h>
#include <cuda_fp16.h>
#include <math.h>
#include <stdint.h>

// MoE dims (fixed)
#define NT 16384
#define DD 512
#define HH 2048
#define EE 8
#define KK 2
#define CAP 8192
#define CROWS (CAP * EE)

// ---------------- device scratch ----------------
__device__ __half g_x16[(size_t)NT * DD];
__device__ __half g_w1t[(size_t)EE * HH * DD];   // [e][h][d] fp16
__device__ __half g_w2t[(size_t)EE * DD * HH];   // [e][d][h] fp16
__device__ __half g_h16[(size_t)CROWS * HH];
__device__ float g_y[(size_t)CROWS * DD];
__device__ int   g_perm[CROWS];
__device__ int   g_rowOf[NT * KK];
__device__ float g_gate2[NT * KK];
__device__ int   g_topi[NT * KK];
__device__ float g_topv[NT * KK];
__device__ int   g_fill[EE];

__device__ __forceinline__ uint32_t smem_u32(const void* p) {
    uint32_t a;
    asm("{ .reg .u64 t; cvta.to.shared.u64 t, %1; cvt.u32.u64 %0, t; }" : "=r"(a) : "l"(p));
    return a;
}
__device__ __forceinline__ void cp16(uint32_t saddr, const void* gaddr, uint32_t sz) {
    asm volatile("cp.async.cg.shared.global [%0], [%1], 16, %2;"
                 :: "r"(saddr), "l"(gaddr), "r"(sz) : "memory");
}
#define CP_COMMIT() asm volatile("cp.async.commit_group;" ::: "memory")

__device__ __forceinline__ void ldsm_x4(uint32_t* r, uint32_t addr) {
    asm volatile("ldmatrix.sync.aligned.m8n8.x4.shared.b16 {%0,%1,%2,%3}, [%4];"
                 : "=r"(r[0]), "=r"(r[1]), "=r"(r[2]), "=r"(r[3]) : "r"(addr));
}
__device__ __forceinline__ void mma16816(float* c, const uint32_t* a, const uint32_t* b) {
    asm volatile(
        "mma.sync.aligned.m16n8k16.row.col.f32.f16.f16.f32 "
        "{%0,%1,%2,%3}, {%4,%5,%6,%7}, {%8,%9}, {%0,%1,%2,%3};"
        : "+f"(c[0]), "+f"(c[1]), "+f"(c[2]), "+f"(c[3])
        : "r"(a[0]), "r"(a[1]), "r"(a[2]), "r"(a[3]), "r"(b[0]), "r"(b[1]));
}

// ---------------- prep: zero counters + convert x + transpose W1,W2 (fp16) ----
__global__ __launch_bounds__(256)
void prep_kernel(const float* __restrict__ x,
                 const float* __restrict__ W1,
                 const float* __restrict__ W2) {
    __shared__ float t[32][33];
    const int b = blockIdx.x;
    const int tid = threadIdx.x;

    if (b < 8192) {
        if (b == 0 && tid < EE) g_fill[tid] = 0;
        int i = b * 256 + tid;
        float4 v = ((const float4*)x)[i];
        __half2* H = (__half2*)g_x16;
        H[i * 2 + 0] = __halves2half2(__float2half_rn(v.x), __float2half_rn(v.y));
        H[i * 2 + 1] = __halves2half2(__float2half_rn(v.z), __float2half_rn(v.w));
        return;
    }

    const bool isW1 = (b < 16384);
    const int  bb   = isW1 ? (b - 8192) : (b - 16384);
    const int  R    = isW1 ? DD : HH;
    const int  C    = isW1 ? HH : DD;
    const int  CB   = C / 32;
    const int  e    = bb / (CB * (R / 32));
    const int  rem  = bb % (CB * (R / 32));
    const int  cb   = rem % CB;
    const int  rb   = rem / CB;
    const int  c0 = cb * 32, r0 = rb * 32;
    const int  tx = tid & 31, ty = tid >> 5;

    const float* s = (isW1 ? W1 : W2) + (size_t)e * R * C;
    __half* dh = (isW1 ? g_w1t : g_w2t) + (size_t)e * R * C;

#pragma unroll
    for (int i = 0; i < 4; i++)
        t[ty + i * 8][tx] = s[(size_t)(r0 + ty + i * 8) * C + c0 + tx];
    __syncthreads();
#pragma unroll
    for (int i = 0; i < 4; i++)
        dh[(size_t)(c0 + ty + i * 8) * R + r0 + tx] = __float2half_rn(t[tx][ty + i * 8]);
}

// ---------------- router ----------------
__global__ __launch_bounds__(256)
void router_kernel(const float* __restrict__ x, const float* __restrict__ Wr) {
    __shared__ float sWrT[EE * DD];
    int tid = threadIdx.x;
    for (int i = tid; i < DD * EE; i += blockDim.x) {
        int d = i / EE, e = i % EE;
        sWrT[e * DD + d] = Wr[i];
    }
    __syncthreads();
    int warp = tid >> 5, lane = tid & 31;
    int n = blockIdx.x * 8 + warp;
    if (n >= NT) return;
    float acc[EE];
#pragma unroll
    for (int e = 0; e < EE; e++) acc[e] = 0.f;
    const float* xr = x + (size_t)n * DD;
#pragma unroll
    for (int it = 0; it < DD / 32; it++) {
        float xv = xr[lane + it * 32];
#pragma unroll
        for (int e = 0; e < EE; e++) acc[e] += xv * sWrT[e * DD + lane + it * 32];
    }
#pragma unroll
    for (int e = 0; e < EE; e++)
#pragma unroll
        for (int s = 16; s > 0; s >>= 1)
            acc[e] += __shfl_xor_sync(0xffffffffu, acc[e], s);
    if (lane == 0) {
        float m = acc[0];
#pragma unroll
        for (int e = 1; e < EE; e++) m = fmaxf(m, acc[e]);
        float p[EE], s = 0.f;
#pragma unroll
        for (int e = 0; e < EE; e++) { p[e] = expf(acc[e] - m); s += p[e]; }
        float inv = 1.f / s;
        int i1 = 0; float v1 = p[0];
#pragma unroll
        for (int e = 1; e < EE; e++) if (p[e] > v1) { v1 = p[e]; i1 = e; }
        int i2 = -1; float v2 = -1.f;
#pragma unroll
        for (int e = 0; e < EE; e++) if (e != i1 && p[e] > v2) { v2 = p[e]; i2 = e; }
        g_topi[2 * n + 0] = i1; g_topv[2 * n + 0] = v1 * inv;
        g_topi[2 * n + 1] = i2; g_topv[2 * n + 1] = v2 * inv;
    }
}

__global__ void scatter_kernel() {
    int i = blockIdx.x * blockDim.x + threadIdx.x;
    if (i >= NT * KK) return;
    int token = i >> 1;
    int e = g_topi[i];
    int pos = atomicAdd(&g_fill[e], 1);
    int row = e * CAP + pos;
    g_perm[row] = token;
    g_rowOf[i] = row;
    g_gate2[i] = g_topv[i];
}

// ---------------- HMMA GEMM: 128x64 CTA tile, 8 warps (32x32), 3 CTAs/SM ----------------
#define ROWB 80
#define A_BYTES (128 * ROWB)            // 10240
#define B_BYTES (64 * ROWB)             // 5120
#define STAGE_BYTES (A_BYTES + B_BYTES) // 15360
#define NSTAGE 3
#define SMEM_GEMM_BYTES (NSTAGE * STAGE_BYTES)   // 46080

template <bool FC1>
__global__ __launch_bounds__(256, 3)
void moe_gemm_hmma_kernel(const float* __restrict__ bias) {
    constexpr int Kd = FC1 ? DD : HH;
    constexpr int Nd = FC1 ? HH : DD;
    constexpr int NCHUNK = Kd / 32;

    extern __shared__ char smem[];
    const int e = blockIdx.z;
    const int cnt = g_fill[e];
    const int m0 = blockIdx.y * 128;
    if (m0 >= cnt) return;
    const int off = e * CAP;
    const int n0 = blockIdx.x * 64;
    const int tid = threadIdx.x;
    const int wid = tid >> 5, lane = tid & 31;

    const __half* aP = FC1 ? g_x16 : g_h16;
    const __half* wB = FC1 ? g_w1t : g_w2t;

    // staging: A: 128 rows x 4 seg, thread -> row tid/2, segs (tid&1)*2+{0,1}
    //          B: 64 rows x 4 seg, thread -> row tid/4, seg tid&3
    const int arow_i = tid >> 1;
    const int apart = tid & 1;
    long long arow;
    {
        int m = m0 + arow_i;
        if (m < cnt) arow = FC1 ? (long long)g_perm[off + m] * DD
                                : (long long)(off + m) * HH;
        else arow = -1;
    }
    const int brow_i = tid >> 2;
    const int bseg = tid & 3;
    const size_t brow = ((size_t)e * Nd + n0 + brow_i) * Kd;

    const uint32_t sb = smem_u32(smem);
    const uint32_t aok = (arow >= 0) ? 16u : 0u;
    const __half* pah = aP + (arow >= 0 ? arow : 0);
    const __half* pbh = wB + brow;
    const uint32_t aOff = arow_i * ROWB + apart * 32;
    const uint32_t bOff = A_BYTES + brow_i * ROWB + bseg * 16;

    auto stage = [&](int c) {
        const uint32_t so = (uint32_t)(c % NSTAGE) * STAGE_BYTES;
        const int k0 = c * 32;
#pragma unroll
        for (int i = 0; i < 2; i++)
            cp16(sb + so + aOff + i * 16, pah + k0 + apart * 16 + i * 8, aok);
        cp16(sb + so + bOff, pbh + k0 + bseg * 8, 16u);
        CP_COMMIT();
    };

    // warp grid: 4 (M) x 2 (N); warp tile 32x32
    const int warpM = (wid >> 1) * 32;
    const int warpN = (wid & 1) * 32;
    const int g = lane >> 3, lr = lane & 7;
    const uint32_t aLaneOff = (uint32_t)(warpM + lr + ((g & 1) << 3)) * ROWB + ((g >> 1) << 4);
    const uint32_t bLaneOff = A_BYTES +
        (uint32_t)(warpN + lr + ((g >> 1) << 3)) * ROWB + ((g & 1) << 4);

    float acc[2][4][4];
#pragma unroll
    for (int i = 0; i < 2; i++)
#pragma unroll
        for (int j = 0; j < 4; j++)
#pragma unroll
            for (int k = 0; k < 4; k++) acc[i][j][k] = 0.f;

    stage(0);
    if (NCHUNK > 1) stage(1);

#pragma unroll 1
    for (int c = 0; c < NCHUNK; c++) {
        if (c + 1 < NCHUNK) asm volatile("cp.async.wait_group 1;" ::: "memory");
        else                asm volatile("cp.async.wait_group 0;" ::: "memory");
        __syncthreads();
        if (c + 2 < NCHUNK) stage(c + 2);

        const uint32_t st = (uint32_t)(c % NSTAGE) * STAGE_BYTES;
#pragma unroll
        for (int ks = 0; ks < 2; ks++) {
            const uint32_t ko = ks * 32;
            uint32_t bh[8];
#pragma unroll
            for (int t = 0; t < 2; t++)
                ldsm_x4(bh + 4 * t, sb + st + ko + bLaneOff + t * 16 * ROWB);
            uint32_t ah[8];
#pragma unroll
            for (int mt = 0; mt < 2; mt++)
                ldsm_x4(ah + 4 * mt, sb + st + ko + aLaneOff + mt * 16 * ROWB);
#pragma unroll
            for (int mt = 0; mt < 2; mt++) {
#pragma unroll
                for (int nf = 0; nf < 4; nf++) {
                    const uint32_t* B = &bh[4 * (nf >> 1) + 2 * (nf & 1)];
                    mma16816(acc[mt][nf], ah + 4 * mt, B);
                }
            }
        }
    }

    // epilogue
    const int rr = lane >> 2;
    const int cc2 = (lane & 3) * 2;
    float bv[4][2];
#pragma unroll
    for (int nf = 0; nf < 4; nf++) {
        int col = n0 + warpN + nf * 8 + cc2;
        bv[nf][0] = __ldg(&bias[(size_t)e * Nd + col]);
        bv[nf][1] = __ldg(&bias[(size_t)e * Nd + col + 1]);
    }
#pragma unroll
    for (int mt = 0; mt < 2; mt++) {
#pragma unroll
        for (int nf = 0; nf < 4; nf++) {
            int col = n0 + warpN + nf * 8 + cc2;
#pragma unroll
            for (int h = 0; h < 2; h++) {
                int m = m0 + warpM + mt * 16 + rr + h * 8;
                if (m < cnt) {
                    float v0 = acc[mt][nf][h * 2 + 0] + bv[nf][0];
                    float v1 = acc[mt][nf][h * 2 + 1] + bv[nf][1];
                    size_t orow = (size_t)(off + m);
                    if (FC1) {
                        v0 = fmaxf(v0, 0.f); v1 = fmaxf(v1, 0.f);
                        *(__half2*)(g_h16 + orow * HH + col) =
                            __halves2half2(__float2half_rn(v0), __float2half_rn(v1));
                    } else {
                        *(float2*)(g_y + orow * DD + col) = make_float2(v0, v1);
                    }
                }
            }
        }
    }
}

// ---------------- combine ----------------
__global__ __launch_bounds__(128)
void combine_kernel(float* __restrict__ out) {
    int n = blockIdx.x;
    int d = threadIdx.x * 4;
    int r0 = g_rowOf[2 * n + 0];
    int r1 = g_rowOf[2 * n + 1];
    float g0 = g_gate2[2 * n + 0];
    float g1 = g_gate2[2 * n + 1];
    float4 y0 = *(const float4*)&g_y[(size_t)r0 * DD + d];
    float4 y1 = *(const float4*)&g_y[(size_t)r1 * DD + d];
    float4 o;
    o.x = g0 * y0.x + g1 * y1.x;
    o.y = g0 * y0.y + g1 * y1.y;
    o.z = g0 * y0.z + g1 * y1.z;
    o.w = g0 * y0.w + g1 * y1.w;
    *(float4*)&out[(size_t)n * DD + d] = o;
}

__global__ void tail_kernel(float* __restrict__ out, long long start, long long total) {
    long long i = start + (long long)blockIdx.x * blockDim.x + threadIdx.x;
    if (i < total) out[i] = 0.f;
}

extern "C" void kernel_launch(void* const* d_in, const int* in_sizes, int n_in,
                              void* d_out, int out_size) {
    const float* x  = (const float*)d_in[0];
    const float* Wr = (const float*)d_in[1];
    const float* W1 = (const float*)d_in[2];
    const float* b1 = (const float*)d_in[3];
    const float* W2 = (const float*)d_in[4];
    const float* b2 = (const float*)d_in[5];
    float* out = (float*)d_out;

    cudaFuncSetAttribute(moe_gemm_hmma_kernel<true>,
                         cudaFuncAttributeMaxDynamicSharedMemorySize, SMEM_GEMM_BYTES);
    cudaFuncSetAttribute(moe_gemm_hmma_kernel<false>,
                         cudaFuncAttributeMaxDynamicSharedMemorySize, SMEM_GEMM_BYTES);

    prep_kernel<<<24576, 256>>>(x, W1, W2);                        // 0
    router_kernel<<<NT / 8, 256>>>(x, Wr);                         // 1
    scatter_kernel<<<(NT * KK + 255) / 256, 256>>>();              // 2
    moe_gemm_hmma_kernel<true ><<<dim3(HH / 64, CAP / 128, EE),    // 3 <- ncu target
                                  256, SMEM_GEMM_BYTES>>>(b1);
    moe_gemm_hmma_kernel<false><<<dim3(DD / 64, CAP / 128, EE),    // 4
                                  256, SMEM_GEMM_BYTES>>>(b2);
    combine_kernel<<<NT, 128>>>(out);                              // 5

    long long main_elems = (long long)NT * DD;
    long long total = (long long)out_size;
    if (total > main_elems) {
        long long tail = total - main_elems;
        int blocks = (int)((tail + 255) / 256);
        tail_kernel<<<blocks, 256>>>(out, main_elems, total);
    }
}

// round 11
// speedup vs baseline: 1.0749x; 1.0749x over previous
#include <cuda_runtime.h>
#include <cuda_fp16.h>
#include <math.h>
#include <stdint.h>

// MoE dims (fixed)
#define NT 16384
#define DD 512
#define HH 2048
#define EE 8
#define KK 2
#define CAP 8192
#define CROWS (CAP * EE)

// ---------------- device scratch ----------------
__device__ __half g_x16[(size_t)NT * DD];
__device__ __half g_w1t[(size_t)EE * HH * DD];   // [e][h][d] fp16
__device__ __half g_w2t[(size_t)EE * DD * HH];   // [e][d][h] fp16
__device__ __half g_h16[(size_t)CROWS * HH];
__device__ float g_y[(size_t)CROWS * DD];
__device__ int   g_perm[CROWS];
__device__ int   g_rowOf[NT * KK];
__device__ float g_gate2[NT * KK];
__device__ int   g_fill[EE];

__device__ __forceinline__ uint32_t smem_u32(const void* p) {
    uint32_t a;
    asm("{ .reg .u64 t; cvta.to.shared.u64 t, %1; cvt.u32.u64 %0, t; }" : "=r"(a) : "l"(p));
    return a;
}
__device__ __forceinline__ void cp16(uint32_t saddr, const void* gaddr, uint32_t sz) {
    asm volatile("cp.async.cg.shared.global [%0], [%1], 16, %2;"
                 :: "r"(saddr), "l"(gaddr), "r"(sz) : "memory");
}
#define CP_COMMIT() asm volatile("cp.async.commit_group;" ::: "memory")

__device__ __forceinline__ void ldsm_x4(uint32_t* r, uint32_t addr) {
    asm volatile("ldmatrix.sync.aligned.m8n8.x4.shared.b16 {%0,%1,%2,%3}, [%4];"
                 : "=r"(r[0]), "=r"(r[1]), "=r"(r[2]), "=r"(r[3]) : "r"(addr));
}
__device__ __forceinline__ void mma16816(float* c, const uint32_t* a, const uint32_t* b) {
    asm volatile(
        "mma.sync.aligned.m16n8k16.row.col.f32.f16.f16.f32 "
        "{%0,%1,%2,%3}, {%4,%5,%6,%7}, {%8,%9}, {%0,%1,%2,%3};"
        : "+f"(c[0]), "+f"(c[1]), "+f"(c[2]), "+f"(c[3])
        : "r"(a[0]), "r"(a[1]), "r"(a[2]), "r"(a[3]), "r"(b[0]), "r"(b[1]));
}

// ---------------- prep: zero counters + convert x + transpose W1,W2 (fp16) ----
__global__ __launch_bounds__(256)
void prep_kernel(const float* __restrict__ x,
                 const float* __restrict__ W1,
                 const float* __restrict__ W2) {
    __shared__ float t[32][33];
    const int b = blockIdx.x;
    const int tid = threadIdx.x;

    if (b < 8192) {
        if (b == 0 && tid < EE) g_fill[tid] = 0;
        int i = b * 256 + tid;
        float4 v = ((const float4*)x)[i];
        __half2* H = (__half2*)g_x16;
        H[i * 2 + 0] = __halves2half2(__float2half_rn(v.x), __float2half_rn(v.y));
        H[i * 2 + 1] = __halves2half2(__float2half_rn(v.z), __float2half_rn(v.w));
        return;
    }

    const bool isW1 = (b < 16384);
    const int  bb   = isW1 ? (b - 8192) : (b - 16384);
    const int  R    = isW1 ? DD : HH;
    const int  C    = isW1 ? HH : DD;
    const int  CB   = C / 32;
    const int  e    = bb / (CB * (R / 32));
    const int  rem  = bb % (CB * (R / 32));
    const int  cb   = rem % CB;
    const int  rb   = rem / CB;
    const int  c0 = cb * 32, r0 = rb * 32;
    const int  tx = tid & 31, ty = tid >> 5;

    const float* s = (isW1 ? W1 : W2) + (size_t)e * R * C;
    __half* dh = (isW1 ? g_w1t : g_w2t) + (size_t)e * R * C;

#pragma unroll
    for (int i = 0; i < 4; i++)
        t[ty + i * 8][tx] = s[(size_t)(r0 + ty + i * 8) * C + c0 + tx];
    __syncthreads();
#pragma unroll
    for (int i = 0; i < 4; i++)
        dh[(size_t)(c0 + ty + i * 8) * R + r0 + tx] = __float2half_rn(t[tx][ty + i * 8]);
}

// ---------------- router + scatter fused (one warp per token) ----------------
__global__ __launch_bounds__(256)
void router_kernel(const float* __restrict__ x, const float* __restrict__ Wr) {
    __shared__ float sWrT[EE * DD];
    int tid = threadIdx.x;
    for (int i = tid; i < DD * EE; i += blockDim.x) {
        int d = i / EE, e = i % EE;
        sWrT[e * DD + d] = Wr[i];
    }
    __syncthreads();
    int warp = tid >> 5, lane = tid & 31;
    int n = blockIdx.x * 8 + warp;
    if (n >= NT) return;
    float acc[EE];
#pragma unroll
    for (int e = 0; e < EE; e++) acc[e] = 0.f;
    const float* xr = x + (size_t)n * DD;
#pragma unroll
    for (int it = 0; it < DD / 32; it++) {
        float xv = xr[lane + it * 32];
#pragma unroll
        for (int e = 0; e < EE; e++) acc[e] += xv * sWrT[e * DD + lane + it * 32];
    }
#pragma unroll
    for (int e = 0; e < EE; e++)
#pragma unroll
        for (int s = 16; s > 0; s >>= 1)
            acc[e] += __shfl_xor_sync(0xffffffffu, acc[e], s);
    if (lane == 0) {
        float m = acc[0];
#pragma unroll
        for (int e = 1; e < EE; e++) m = fmaxf(m, acc[e]);
        float p[EE], s = 0.f;
#pragma unroll
        for (int e = 0; e < EE; e++) { p[e] = expf(acc[e] - m); s += p[e]; }
        float inv = 1.f / s;
        int i1 = 0; float v1 = p[0];
#pragma unroll
        for (int e = 1; e < EE; e++) if (p[e] > v1) { v1 = p[e]; i1 = e; }
        int i2 = -1; float v2 = -1.f;
#pragma unroll
        for (int e = 0; e < EE; e++) if (e != i1 && p[e] > v2) { v2 = p[e]; i2 = e; }
        // fused scatter
        int pos1 = atomicAdd(&g_fill[i1], 1);
        int row1 = i1 * CAP + pos1;
        g_perm[row1] = n;
        g_rowOf[2 * n + 0] = row1;
        g_gate2[2 * n + 0] = v1 * inv;
        int pos2 = atomicAdd(&g_fill[i2], 1);
        int row2 = i2 * CAP + pos2;
        g_perm[row2] = n;
        g_rowOf[2 * n + 1] = row2;
        g_gate2[2 * n + 1] = v2 * inv;
    }
}

// ---------------- HMMA GEMM: 128x128 CTA tile, 8 warps (32x64), K-chunk 32, 5 stages ----
#define ROWB 80
#define ARR_BYTES (128 * ROWB)          // 10240
#define STAGE_BYTES (2 * ARR_BYTES)     // A, B : 20480
#define NSTAGE 5
#define SMEM_GEMM_BYTES (NSTAGE * STAGE_BYTES)   // 102400

template <bool FC1>
__global__ __launch_bounds__(256, 2)
void moe_gemm_hmma_kernel(const float* __restrict__ bias) {
    constexpr int Kd = FC1 ? DD : HH;
    constexpr int Nd = FC1 ? HH : DD;
    constexpr int NCHUNK = Kd / 32;

    extern __shared__ char smem[];
    const int e = blockIdx.z;
    const int cnt = g_fill[e];
    const int m0 = blockIdx.y * 128;
    if (m0 >= cnt) return;
    const int off = e * CAP;
    const int n0 = blockIdx.x * 128;
    const int tid = threadIdx.x;
    const int wid = tid >> 5, lane = tid & 31;

    const __half* aP = FC1 ? g_x16 : g_h16;
    const __half* wB = FC1 ? g_w1t : g_w2t;

    // staging: thread -> row = tid/2, 2 of 4 16B segments per array
    const int srow = tid >> 1;
    const int part = tid & 1;
    long long arow;
    {
        int m = m0 + srow;
        if (m < cnt) arow = FC1 ? (long long)g_perm[off + m] * DD
                                : (long long)(off + m) * HH;
        else arow = -1;
    }
    const size_t brow = ((size_t)e * Nd + n0 + srow) * Kd;

    const uint32_t sb = smem_u32(smem);
    const uint32_t rowoff = srow * ROWB + part * 32;
    const uint32_t aok = (arow >= 0) ? 16u : 0u;
    const __half* pah = aP + (arow >= 0 ? arow : 0);
    const __half* pbh = wB + brow;

    auto stage = [&](int c) {
        const uint32_t so = (uint32_t)(c % NSTAGE) * STAGE_BYTES + rowoff;
        const int k0 = c * 32 + part * 16;
#pragma unroll
        for (int i = 0; i < 2; i++) {
            int ke = k0 + i * 8;
            cp16(sb + so             + i * 16, pah + ke, aok);
            cp16(sb + so + ARR_BYTES + i * 16, pbh + ke, 16u);
        }
        CP_COMMIT();
    };

    // warp grid: 4 (M) x 2 (N); warp tile 32x64
    const int warpM = (wid >> 1) * 32;
    const int warpN = (wid & 1) * 64;
    const int g = lane >> 3, lr = lane & 7;
    const uint32_t aLaneOff = (uint32_t)(warpM + lr + ((g & 1) << 3)) * ROWB + ((g >> 1) << 4);
    const uint32_t bLaneOff = (uint32_t)(warpN + lr + ((g >> 1) << 3)) * ROWB + ((g & 1) << 4);

    float acc[2][8][4];
#pragma unroll
    for (int i = 0; i < 2; i++)
#pragma unroll
        for (int j = 0; j < 8; j++)
#pragma unroll
            for (int k = 0; k < 4; k++) acc[i][j][k] = 0.f;

    stage(0);
    if (NCHUNK > 1) stage(1);
    if (NCHUNK > 2) stage(2);
    if (NCHUNK > 3) stage(3);

#pragma unroll 1
    for (int c = 0; c < NCHUNK; c++) {
        if (c + 3 < NCHUNK)      asm volatile("cp.async.wait_group 3;" ::: "memory");
        else if (c + 2 < NCHUNK) asm volatile("cp.async.wait_group 2;" ::: "memory");
        else if (c + 1 < NCHUNK) asm volatile("cp.async.wait_group 1;" ::: "memory");
        else                     asm volatile("cp.async.wait_group 0;" ::: "memory");
        __syncthreads();
        if (c + 4 < NCHUNK) stage(c + 4);

        const uint32_t st = (uint32_t)(c % NSTAGE) * STAGE_BYTES;
        const uint32_t sA = sb + st;
        const uint32_t sB = sA + ARR_BYTES;
#pragma unroll
        for (int ks = 0; ks < 2; ks++) {
            const uint32_t ko = ks * 32;
            uint32_t bh[16];
#pragma unroll
            for (int t = 0; t < 4; t++)
                ldsm_x4(bh + 4 * t, sB + ko + bLaneOff + t * 16 * ROWB);
            uint32_t ah[8];
#pragma unroll
            for (int mt = 0; mt < 2; mt++)
                ldsm_x4(ah + 4 * mt, sA + ko + aLaneOff + mt * 16 * ROWB);
#pragma unroll
            for (int mt = 0; mt < 2; mt++) {
#pragma unroll
                for (int nf = 0; nf < 8; nf++) {
                    const uint32_t* B = &bh[4 * (nf >> 1) + 2 * (nf & 1)];
                    mma16816(acc[mt][nf], ah + 4 * mt, B);
                }
            }
        }
    }

    // epilogue
    const int rr = lane >> 2;
    const int cc2 = (lane & 3) * 2;
    float bv[8][2];
#pragma unroll
    for (int nf = 0; nf < 8; nf++) {
        int col = n0 + warpN + nf * 8 + cc2;
        bv[nf][0] = __ldg(&bias[(size_t)e * Nd + col]);
        bv[nf][1] = __ldg(&bias[(size_t)e * Nd + col + 1]);
    }
#pragma unroll
    for (int mt = 0; mt < 2; mt++) {
#pragma unroll
        for (int nf = 0; nf < 8; nf++) {
            int col = n0 + warpN + nf * 8 + cc2;
#pragma unroll
            for (int h = 0; h < 2; h++) {
                int m = m0 + warpM + mt * 16 + rr + h * 8;
                if (m < cnt) {
                    float v0 = acc[mt][nf][h * 2 + 0] + bv[nf][0];
                    float v1 = acc[mt][nf][h * 2 + 1] + bv[nf][1];
                    size_t orow = (size_t)(off + m);
                    if (FC1) {
                        v0 = fmaxf(v0, 0.f); v1 = fmaxf(v1, 0.f);
                        *(__half2*)(g_h16 + orow * HH + col) =
                            __halves2half2(__float2half_rn(v0), __float2half_rn(v1));
                    } else {
                        *(float2*)(g_y + orow * DD + col) = make_float2(v0, v1);
                    }
                }
            }
        }
    }
}

// ---------------- combine ----------------
__global__ __launch_bounds__(128)
void combine_kernel(float* __restrict__ out) {
    int n = blockIdx.x;
    int d = threadIdx.x * 4;
    int r0 = g_rowOf[2 * n + 0];
    int r1 = g_rowOf[2 * n + 1];
    float g0 = g_gate2[2 * n + 0];
    float g1 = g_gate2[2 * n + 1];
    float4 y0 = *(const float4*)&g_y[(size_t)r0 * DD + d];
    float4 y1 = *(const float4*)&g_y[(size_t)r1 * DD + d];
    float4 o;
    o.x = g0 * y0.x + g1 * y1.x;
    o.y = g0 * y0.y + g1 * y1.y;
    o.z = g0 * y0.z + g1 * y1.z;
    o.w = g0 * y0.w + g1 * y1.w;
    *(float4*)&out[(size_t)n * DD + d] = o;
}

__global__ void tail_kernel(float* __restrict__ out, long long start, long long total) {
    long long i = start + (long long)blockIdx.x * blockDim.x + threadIdx.x;
    if (i < total) out[i] = 0.f;
}

extern "C" void kernel_launch(void* const* d_in, const int* in_sizes, int n_in,
                              void* d_out, int out_size) {
    const float* x  = (const float*)d_in[0];
    const float* Wr = (const float*)d_in[1];
    const float* W1 = (const float*)d_in[2];
    const float* b1 = (const float*)d_in[3];
    const float* W2 = (const float*)d_in[4];
    const float* b2 = (const float*)d_in[5];
    float* out = (float*)d_out;

    cudaFuncSetAttribute(moe_gemm_hmma_kernel<true>,
                         cudaFuncAttributeMaxDynamicSharedMemorySize, SMEM_GEMM_BYTES);
    cudaFuncSetAttribute(moe_gemm_hmma_kernel<false>,
                         cudaFuncAttributeMaxDynamicSharedMemorySize, SMEM_GEMM_BYTES);

    prep_kernel<<<24576, 256>>>(x, W1, W2);                        // 0
    router_kernel<<<NT / 8, 256>>>(x, Wr);                         // 1 (scatter fused)
    moe_gemm_hmma_kernel<true ><<<dim3(HH / 128, CAP / 128, EE),   // 2
                                  256, SMEM_GEMM_BYTES>>>(b1);
    moe_gemm_hmma_kernel<false><<<dim3(DD / 128, CAP / 128, EE),   // 3 <- ncu target
                                  256, SMEM_GEMM_BYTES>>>(b2);
    combine_kernel<<<NT, 128>>>(out);                              // 4

    long long main_elems = (long long)NT * DD;
    long long total = (long long)out_size;
    if (total > main_elems) {
        long long tail = total - main_elems;
        int blocks = (int)((tail + 255) / 256);
        tail_kernel<<<blocks, 256>>>(out, main_elems, total);
    }
}

// round 12
// speedup vs baseline: 1.1161x; 1.0383x over previous
#include <cuda_runtime.h>
#include <cuda_fp16.h>
#include <math.h>
#include <stdint.h>

// MoE dims (fixed)
#define NT 16384
#define DD 512
#define HH 2048
#define EE 8
#define KK 2
#define CAP 8192
#define CROWS (CAP * EE)

// ---------------- device scratch ----------------
__device__ __half g_x16[(size_t)NT * DD];
__device__ __half g_w1t[(size_t)EE * HH * DD];   // [e][h][d] fp16
__device__ __half g_w2t[(size_t)EE * DD * HH];   // [e][d][h] fp16
__device__ __half g_h16[(size_t)CROWS * HH];
__device__ float g_y[(size_t)CROWS * DD];
__device__ int   g_perm[CROWS];
__device__ int   g_rowOf[NT * KK];
__device__ float g_gate2[NT * KK];
__device__ int   g_fill[EE];
__device__ int   g_tile1;     // persistent work counters
__device__ int   g_tile2;

__device__ __forceinline__ uint32_t smem_u32(const void* p) {
    uint32_t a;
    asm("{ .reg .u64 t; cvta.to.shared.u64 t, %1; cvt.u32.u64 %0, t; }" : "=r"(a) : "l"(p));
    return a;
}
__device__ __forceinline__ void cp16(uint32_t saddr, const void* gaddr, uint32_t sz) {
    asm volatile("cp.async.cg.shared.global [%0], [%1], 16, %2;"
                 :: "r"(saddr), "l"(gaddr), "r"(sz) : "memory");
}
#define CP_COMMIT() asm volatile("cp.async.commit_group;" ::: "memory")

__device__ __forceinline__ void ldsm_x4(uint32_t* r, uint32_t addr) {
    asm volatile("ldmatrix.sync.aligned.m8n8.x4.shared.b16 {%0,%1,%2,%3}, [%4];"
                 : "=r"(r[0]), "=r"(r[1]), "=r"(r[2]), "=r"(r[3]) : "r"(addr));
}
__device__ __forceinline__ void mma16816(float* c, const uint32_t* a, const uint32_t* b) {
    asm volatile(
        "mma.sync.aligned.m16n8k16.row.col.f32.f16.f16.f32 "
        "{%0,%1,%2,%3}, {%4,%5,%6,%7}, {%8,%9}, {%0,%1,%2,%3};"
        : "+f"(c[0]), "+f"(c[1]), "+f"(c[2]), "+f"(c[3])
        : "r"(a[0]), "r"(a[1]), "r"(a[2]), "r"(a[3]), "r"(b[0]), "r"(b[1]));
}

// ---------------- prep: zero counters + transpose W1,W2 (fp16) ----------------
// blocks [0,8192): W1    [8192,16384): W2
__global__ __launch_bounds__(256)
void prep_kernel(const float* __restrict__ W1, const float* __restrict__ W2) {
    __shared__ float t[32][33];
    const int b = blockIdx.x;
    const int tid = threadIdx.x;

    if (b == 0 && tid < EE + 2) {
        if (tid < EE) g_fill[tid] = 0;
        else if (tid == EE) g_tile1 = 0;
        else g_tile2 = 0;
    }

    const bool isW1 = (b < 8192);
    const int  bb   = isW1 ? b : (b - 8192);
    const int  R    = isW1 ? DD : HH;
    const int  C    = isW1 ? HH : DD;
    const int  CB   = C / 32;
    const int  e    = bb / (CB * (R / 32));
    const int  rem  = bb % (CB * (R / 32));
    const int  cb   = rem % CB;
    const int  rb   = rem / CB;
    const int  c0 = cb * 32, r0 = rb * 32;
    const int  tx = tid & 31, ty = tid >> 5;

    const float* s = (isW1 ? W1 : W2) + (size_t)e * R * C;
    __half* dh = (isW1 ? g_w1t : g_w2t) + (size_t)e * R * C;

#pragma unroll
    for (int i = 0; i < 4; i++)
        t[ty + i * 8][tx] = s[(size_t)(r0 + ty + i * 8) * C + c0 + tx];
    __syncthreads();
#pragma unroll
    for (int i = 0; i < 4; i++)
        dh[(size_t)(c0 + ty + i * 8) * R + r0 + tx] = __float2half_rn(t[tx][ty + i * 8]);
}

// ---------------- router + scatter + x-convert fused (one warp per token) ----------------
__global__ __launch_bounds__(256)
void router_kernel(const float* __restrict__ x, const float* __restrict__ Wr) {
    __shared__ float sWrT[EE * DD];
    int tid = threadIdx.x;
    for (int i = tid; i < DD * EE; i += blockDim.x) {
        int d = i / EE, e = i % EE;
        sWrT[e * DD + d] = Wr[i];
    }
    __syncthreads();
    int warp = tid >> 5, lane = tid & 31;
    int n = blockIdx.x * 8 + warp;
    if (n >= NT) return;
    float acc[EE];
#pragma unroll
    for (int e = 0; e < EE; e++) acc[e] = 0.f;
    const float* xr = x + (size_t)n * DD;
    __half* xh = g_x16 + (size_t)n * DD;
#pragma unroll
    for (int it = 0; it < DD / 32; it++) {
        float xv = xr[lane + it * 32];
        xh[lane + it * 32] = __float2half_rn(xv);      // fused fp16 convert
#pragma unroll
        for (int e = 0; e < EE; e++) acc[e] += xv * sWrT[e * DD + lane + it * 32];
    }
#pragma unroll
    for (int e = 0; e < EE; e++)
#pragma unroll
        for (int s = 16; s > 0; s >>= 1)
            acc[e] += __shfl_xor_sync(0xffffffffu, acc[e], s);
    if (lane == 0) {
        float m = acc[0];
#pragma unroll
        for (int e = 1; e < EE; e++) m = fmaxf(m, acc[e]);
        float p[EE], s = 0.f;
#pragma unroll
        for (int e = 0; e < EE; e++) { p[e] = expf(acc[e] - m); s += p[e]; }
        float inv = 1.f / s;
        int i1 = 0; float v1 = p[0];
#pragma unroll
        for (int e = 1; e < EE; e++) if (p[e] > v1) { v1 = p[e]; i1 = e; }
        int i2 = -1; float v2 = -1.f;
#pragma unroll
        for (int e = 0; e < EE; e++) if (e != i1 && p[e] > v2) { v2 = p[e]; i2 = e; }
        int pos1 = atomicAdd(&g_fill[i1], 1);
        int row1 = i1 * CAP + pos1;
        g_perm[row1] = n;
        g_rowOf[2 * n + 0] = row1;
        g_gate2[2 * n + 0] = v1 * inv;
        int pos2 = atomicAdd(&g_fill[i2], 1);
        int row2 = i2 * CAP + pos2;
        g_perm[row2] = n;
        g_rowOf[2 * n + 1] = row2;
        g_gate2[2 * n + 1] = v2 * inv;
    }
}

// ---------------- persistent HMMA GEMM: 128x128 tile, 8 warps (32x64), 5-stage ----------
#define ROWB 80
#define ARR_BYTES (128 * ROWB)          // 10240
#define STAGE_BYTES (2 * ARR_BYTES)     // 20480
#define NSTAGE 5
#define SMEM_GEMM_BYTES (NSTAGE * STAGE_BYTES + 128)  // +tile broadcast slot
#define NPERSIST 296                    // 2 CTAs x 148 SMs

template <bool FC1>
__global__ __launch_bounds__(256, 2)
void moe_gemm_hmma_kernel(const float* __restrict__ bias) {
    constexpr int Kd = FC1 ? DD : HH;
    constexpr int Nd = FC1 ? HH : DD;
    constexpr int NCHUNK = Kd / 32;
    constexpr int NTILES = Nd / 128;

    extern __shared__ char smem[];
    int* stile = (int*)(smem + NSTAGE * STAGE_BYTES);
    const int tid = threadIdx.x;
    const int wid = tid >> 5, lane = tid & 31;

    const __half* aP = FC1 ? g_x16 : g_h16;
    const __half* wB = FC1 ? g_w1t : g_w2t;
    int* ctr = FC1 ? &g_tile1 : &g_tile2;

    // total tile count (g_fill stable during this kernel)
    int total = 0;
#pragma unroll
    for (int e = 0; e < EE; e++)
        total += ((g_fill[e] + 127) >> 7) * NTILES;

    const int srow = tid >> 1;
    const int part = tid & 1;
    const uint32_t sb = smem_u32(smem);
    const uint32_t rowoff = srow * ROWB + part * 32;

    // warp grid: 4 (M) x 2 (N); warp tile 32x64
    const int warpM = (wid >> 1) * 32;
    const int warpN = (wid & 1) * 64;
    const int g = lane >> 3, lr = lane & 7;
    const uint32_t aLaneOff = (uint32_t)(warpM + lr + ((g & 1) << 3)) * ROWB + ((g >> 1) << 4);
    const uint32_t bLaneOff = (uint32_t)(warpN + lr + ((g >> 1) << 3)) * ROWB + ((g & 1) << 4);
    const int rr = lane >> 2;
    const int cc2 = (lane & 3) * 2;

#pragma unroll 1
    while (true) {
        if (tid == 0) *stile = atomicAdd(ctr, 1);
        __syncthreads();
        const int t = *stile;
        if (t >= total) break;

        // decode tile -> (e, m0, n0); nt fastest for A-tile reuse
        int rem = t, e = 0;
#pragma unroll 1
        for (; e < EE - 1; e++) {
            int te = ((g_fill[e] + 127) >> 7) * NTILES;
            if (rem < te) break;
            rem -= te;
        }
        const int cnt = g_fill[e];
        const int m0 = (rem / NTILES) * 128;
        const int n0 = (rem % NTILES) * 128;
        const int off = e * CAP;

        long long arow;
        {
            int m = m0 + srow;
            if (m < cnt) arow = FC1 ? (long long)g_perm[off + m] * DD
                                    : (long long)(off + m) * HH;
            else arow = -1;
        }
        const uint32_t aok = (arow >= 0) ? 16u : 0u;
        const __half* pah = aP + (arow >= 0 ? arow : 0);
        const __half* pbh = wB + ((size_t)e * Nd + n0 + srow) * Kd;

        auto stage = [&](int c) {
            const uint32_t so = (uint32_t)(c % NSTAGE) * STAGE_BYTES + rowoff;
            const int k0 = c * 32 + part * 16;
#pragma unroll
            for (int i = 0; i < 2; i++) {
                int ke = k0 + i * 8;
                cp16(sb + so             + i * 16, pah + ke, aok);
                cp16(sb + so + ARR_BYTES + i * 16, pbh + ke, 16u);
            }
            CP_COMMIT();
        };

        float acc[2][8][4];
#pragma unroll
        for (int i = 0; i < 2; i++)
#pragma unroll
            for (int j = 0; j < 8; j++)
#pragma unroll
                for (int k = 0; k < 4; k++) acc[i][j][k] = 0.f;

        stage(0);
        stage(1);
        stage(2);
        stage(3);

#pragma unroll 1
        for (int c = 0; c < NCHUNK; c++) {
            if (c + 3 < NCHUNK)      asm volatile("cp.async.wait_group 3;" ::: "memory");
            else if (c + 2 < NCHUNK) asm volatile("cp.async.wait_group 2;" ::: "memory");
            else if (c + 1 < NCHUNK) asm volatile("cp.async.wait_group 1;" ::: "memory");
            else                     asm volatile("cp.async.wait_group 0;" ::: "memory");
            __syncthreads();
            if (c + 4 < NCHUNK) stage(c + 4);

            const uint32_t st = (uint32_t)(c % NSTAGE) * STAGE_BYTES;
            const uint32_t sA = sb + st;
            const uint32_t sB = sA + ARR_BYTES;
#pragma unroll
            for (int ks = 0; ks < 2; ks++) {
                const uint32_t ko = ks * 32;
                uint32_t bh[16];
#pragma unroll
                for (int tt = 0; tt < 4; tt++)
                    ldsm_x4(bh + 4 * tt, sB + ko + bLaneOff + tt * 16 * ROWB);
                uint32_t ah[8];
#pragma unroll
                for (int mt = 0; mt < 2; mt++)
                    ldsm_x4(ah + 4 * mt, sA + ko + aLaneOff + mt * 16 * ROWB);
#pragma unroll
                for (int mt = 0; mt < 2; mt++) {
#pragma unroll
                    for (int nf = 0; nf < 8; nf++) {
                        const uint32_t* B = &bh[4 * (nf >> 1) + 2 * (nf & 1)];
                        mma16816(acc[mt][nf], ah + 4 * mt, B);
                    }
                }
            }
        }

        // epilogue
#pragma unroll
        for (int mt = 0; mt < 2; mt++) {
#pragma unroll
            for (int nf = 0; nf < 8; nf++) {
                int col = n0 + warpN + nf * 8 + cc2;
                float bv0 = __ldg(&bias[(size_t)e * Nd + col]);
                float bv1 = __ldg(&bias[(size_t)e * Nd + col + 1]);
#pragma unroll
                for (int h = 0; h < 2; h++) {
                    int m = m0 + warpM + mt * 16 + rr + h * 8;
                    if (m < cnt) {
                        float v0 = acc[mt][nf][h * 2 + 0] + bv0;
                        float v1 = acc[mt][nf][h * 2 + 1] + bv1;
                        size_t orow = (size_t)(off + m);
                        if (FC1) {
                            v0 = fmaxf(v0, 0.f); v1 = fmaxf(v1, 0.f);
                            *(__half2*)(g_h16 + orow * HH + col) =
                                __halves2half2(__float2half_rn(v0), __float2half_rn(v1));
                        } else {
                            *(float2*)(g_y + orow * DD + col) = make_float2(v0, v1);
                        }
                    }
                }
            }
        }
        // top-of-loop __syncthreads orders epilogue vs next tile fetch
    }
}

// ---------------- combine ----------------
__global__ __launch_bounds__(128)
void combine_kernel(float* __restrict__ out) {
    int n = blockIdx.x;
    int d = threadIdx.x * 4;
    int r0 = g_rowOf[2 * n + 0];
    int r1 = g_rowOf[2 * n + 1];
    float g0 = g_gate2[2 * n + 0];
    float g1 = g_gate2[2 * n + 1];
    float4 y0 = *(const float4*)&g_y[(size_t)r0 * DD + d];
    float4 y1 = *(const float4*)&g_y[(size_t)r1 * DD + d];
    float4 o;
    o.x = g0 * y0.x + g1 * y1.x;
    o.y = g0 * y0.y + g1 * y1.y;
    o.z = g0 * y0.z + g1 * y1.z;
    o.w = g0 * y0.w + g1 * y1.w;
    *(float4*)&out[(size_t)n * DD + d] = o;
}

__global__ void tail_kernel(float* __restrict__ out, long long start, long long total) {
    long long i = start + (long long)blockIdx.x * blockDim.x + threadIdx.x;
    if (i < total) out[i] = 0.f;
}

extern "C" void kernel_launch(void* const* d_in, const int* in_sizes, int n_in,
                              void* d_out, int out_size) {
    const float* x  = (const float*)d_in[0];
    const float* Wr = (const float*)d_in[1];
    const float* W1 = (const float*)d_in[2];
    const float* b1 = (const float*)d_in[3];
    const float* W2 = (const float*)d_in[4];
    const float* b2 = (const float*)d_in[5];
    float* out = (float*)d_out;

    cudaFuncSetAttribute(moe_gemm_hmma_kernel<true>,
                         cudaFuncAttributeMaxDynamicSharedMemorySize, SMEM_GEMM_BYTES);
    cudaFuncSetAttribute(moe_gemm_hmma_kernel<false>,
                         cudaFuncAttributeMaxDynamicSharedMemorySize, SMEM_GEMM_BYTES);

    prep_kernel<<<16384, 256>>>(W1, W2);                       // 0
    router_kernel<<<NT / 8, 256>>>(x, Wr);                     // 1 (scatter + x16 fused)
    moe_gemm_hmma_kernel<true ><<<NPERSIST, 256, SMEM_GEMM_BYTES>>>(b1);   // 2
    moe_gemm_hmma_kernel<false><<<NPERSIST, 256, SMEM_GEMM_BYTES>>>(b2);   // 3 <- ncu
    combine_kernel<<<NT, 128>>>(out);                          // 4

    long long main_elems = (long long)NT * DD;
    long long total = (long long)out_size;
    if (total > main_elems) {
        long long tail = total - main_elems;
        int blocks = (int)((tail + 255) / 256);
        tail_kernel<<<blocks, 256>>>(out, main_elems, total);
    }
}